// round 2
// baseline (speedup 1.0000x reference)
#include <cuda_runtime.h>
#include <math.h>

#define NM    512
#define NT    64
#define NH1   256
#define NH2   128
#define STEPS 20
#define NBLK  148
#define NTHR  512
#define NTAY  9      // Taylor degree for expm action; remainder < 1e-9 at ||Omega|| <= 0.5

// ----------------- device scratch (allocation is forbidden) -----------------
__device__ float g_Omega[NM * NM];
__device__ float g_v[NM];          // state entering current step
__device__ float g_t[2][NM];       // Taylor term double buffer
__device__ float g_acc[NM];        // expm(Omega) @ v accumulator
__device__ float g_h1p[32 * NH1];  // MLP layer-1 partials
__device__ float g_soft[NT];
__device__ int   g_done;
__device__ int   g_tgt;
__device__ unsigned int g_cnt;     // barrier counter: starts 0, self-restoring
__device__ unsigned int g_gen;     // barrier generation: monotonic across replays

// Sense-reversing grid barrier. Valid because all NBLK=148 CTAs are co-resident
// (grid <= SM count, occupancy >= 1). __threadfence (gpu scope) also invalidates
// L1 on this SM (CCTL.IVALL), but cross-block reads below still use __ldcg/volatile.
__device__ __forceinline__ void grid_sync() {
    __syncthreads();
    if (threadIdx.x == 0) {
        __threadfence();                                   // release (cumulative after bar.sync)
        unsigned int gen = *(volatile unsigned int*)&g_gen;
        if (atomicAdd(&g_cnt, 1u) == NBLK - 1u) {
            g_cnt = 0u;
            __threadfence();
            *(volatile unsigned int*)&g_gen = gen + 1u;
        } else {
            while (*(volatile unsigned int*)&g_gen == gen) { }
        }
        __threadfence();                                   // acquire
    }
    __syncthreads();
}

__global__ void __launch_bounds__(NTHR, 1)
petri_kernel(const float* __restrict__ v_src,  const float* __restrict__ v_target,
             const float* __restrict__ omegas, const float* __restrict__ W1,
             const float* __restrict__ b1,     const float* __restrict__ W2,
             const float* __restrict__ b2,     const float* __restrict__ W3,
             const float* __restrict__ b3,     const float* __restrict__ gumbel,
             float* __restrict__ out)
{
    __shared__ float s_x[2 * NM];
    __shared__ float s_rv[NTHR];
    __shared__ int   s_ri[NTHR];
    __shared__ float s_h1[NH1];
    __shared__ float s_p2[4 * NH2];
    __shared__ float s_h2[NH2];
    __shared__ float s_p3[4 * NT];
    __shared__ float s_lg[NT];
    __shared__ float s_soft[NT];
    __shared__ int   s_dn;

    const int tid  = threadIdx.x;
    const int bid  = blockIdx.x;
    const int lane = tid & 31;
    const int warp = tid >> 5;

    // ---------------- init: tgt = argmax(v_target), v = v_src, done = 0 ----------------
    if (bid == 0) {
        g_v[tid] = v_src[tid];
        s_rv[tid] = v_target[tid];
        s_ri[tid] = tid;
        __syncthreads();
        for (int off = NTHR / 2; off > 0; off >>= 1) {
            if (tid < off) {
                float ov = s_rv[tid + off]; int oi = s_ri[tid + off];
                if (ov > s_rv[tid]) { s_rv[tid] = ov; s_ri[tid] = oi; }  // ties keep lower idx
            }
            __syncthreads();
        }
        if (tid == 0) {
            *(volatile int*)&g_tgt  = s_ri[0];
            *(volatile int*)&g_done = 0;
        }
    }
    grid_sync();

    // ------------------------------------ scan ------------------------------------
    for (int s = 0; s < STEPS; ++s) {
        // ---- P1: MLP layer 1 partials (blocks 0..15) ----
        if (bid < 16) {
            s_x[tid]      = __ldcg(&g_v[tid]);
            s_x[NM + tid] = v_target[tid];
            __syncthreads();
            const int gw = bid * 16 + warp;     // 0..255
            const int jg = gw & 7;              // 8 col groups of 32
            const int ic = gw >> 3;             // 32 row chunks of 32
            const int j  = jg * 32 + lane;
            const float* w1p = W1 + (ic * 32) * NH1 + j;
            const float* xp  = s_x + ic * 32;
            float p = 0.f;
            #pragma unroll
            for (int i = 0; i < 32; ++i) p += xp[i] * w1p[i * NH1];
            g_h1p[ic * NH1 + j] = p;
        }
        grid_sync();

        // ---- P2: MLP tail + logits + gumbel softmax (block 0) ----
        if (bid == 0) {
            if (tid == 0) s_dn = *(volatile int*)&g_done;   // done at step entry
            if (tid < NH1) {
                float h = b1[tid];
                #pragma unroll 8
                for (int ic = 0; ic < 32; ++ic) h += __ldcg(&g_h1p[ic * NH1 + tid]);
                s_h1[tid] = fmaxf(h, 0.f);
            }
            __syncthreads();
            {   // L2: 128 outs x 256 in
                const int jg = warp & 3, rc = warp >> 2;
                const int j  = jg * 32 + lane;
                const float* w2p = W2 + (rc * 64) * NH2 + j;
                const float* hp  = s_h1 + rc * 64;
                float p = 0.f;
                #pragma unroll 8
                for (int i = 0; i < 64; ++i) p += hp[i] * w2p[i * NH2];
                s_p2[rc * NH2 + j] = p;
            }
            __syncthreads();
            if (tid < NH2) {
                float h = s_p2[tid] + s_p2[NH2 + tid] + s_p2[2 * NH2 + tid]
                        + s_p2[3 * NH2 + tid] + b2[tid];
                s_h2[tid] = fmaxf(h, 0.f);
            }
            __syncthreads();
            if (warp < 8) {  // L3: 64 outs x 128 in
                const int jg = warp & 1, rc = warp >> 1;
                const int j  = jg * 32 + lane;
                const float* w3p = W3 + (rc * 32) * NT + j;
                const float* hp  = s_h2 + rc * 32;
                float p = 0.f;
                #pragma unroll 8
                for (int i = 0; i < 32; ++i) p += hp[i] * w3p[i * NT];
                s_p3[rc * NT + j] = p;
            }
            __syncthreads();
            if (tid < NT) {
                float lg = s_p3[tid] + s_p3[NT + tid] + s_p3[2 * NT + tid]
                         + s_p3[3 * NT + tid] + b3[tid];
                out[NM + s * NT + tid] = s_dn ? 0.f : lg;   // logits zeroed once done
                s_lg[tid] = lg + gumbel[s * NT + tid];      // TAU = 1
            }
            __syncthreads();
            if (tid == 0) {                                  // serial softmax: fixed order, 64 elems
                float mx = s_lg[0];
                for (int t = 1; t < NT; ++t) mx = fmaxf(mx, s_lg[t]);
                float ssum = 0.f;
                for (int t = 0; t < NT; ++t) { float e = expf(s_lg[t] - mx); s_soft[t] = e; ssum += e; }
                float inv = 1.f / ssum;
                for (int t = 0; t < NT; ++t) g_soft[t] = s_soft[t] * inv;
            }
        }
        grid_sync();

        // ---- P3: Omega = sum_t soft[t] * A_t  (all blocks), init Taylor state ----
        {
            if (tid < NT) s_soft[tid] = __ldcg(&g_soft[tid]);
            __syncthreads();
            const float4* om4 = (const float4*)omegas;
            float4* O4 = (float4*)g_Omega;
            const int n4 = NM * NM / 4;                       // 65536
            for (int e = bid * NTHR + tid; e < n4; e += NBLK * NTHR) {
                float4 a = make_float4(0.f, 0.f, 0.f, 0.f);
                #pragma unroll 8
                for (int t = 0; t < NT; ++t) {
                    const float sc = s_soft[t];
                    const float4 w = __ldg(&om4[t * n4 + e]);
                    a.x += sc * w.x; a.y += sc * w.y; a.z += sc * w.z; a.w += sc * w.w;
                }
                O4[e] = a;
            }
            if (bid == NBLK - 1) {                            // acc = v, t0 = v
                float v = __ldcg(&g_v[tid]);
                g_t[0][tid] = v;
                g_acc[tid]  = v;
            }
        }
        grid_sync();

        // ---- P4: Taylor action, term k: t_k = Omega @ t_{k-1} / k ; acc += t_k ----
        for (int k = 1; k <= NTAY; ++k) {
            if (bid < 32) {                                   // 512 warps = one row each
                const int row = bid * 16 + warp;
                const float* Orow = g_Omega + row * NM;
                const float* wv   = g_t[(k - 1) & 1];
                float p = 0.f;
                #pragma unroll
                for (int i = 0; i < 16; ++i) {
                    const int j = lane + 32 * i;
                    p += __ldcg(&Orow[j]) * __ldcg(&wv[j]);   // L1 bypass: written by other SMs
                }
                #pragma unroll
                for (int o = 16; o > 0; o >>= 1) p += __shfl_down_sync(0xffffffffu, p, o);
                if (lane == 0) {
                    const float wn = p * (1.0f / (float)k);
                    g_t[k & 1][row] = wn;
                    g_acc[row] = __ldcg(&g_acc[row]) + wn;
                }
            }
            grid_sync();
        }

        // ---- P5: done_new = done | (argmax(v_new)==tgt); v = done ? v : v_new ----
        if (bid == 0) {
            const float av = __ldcg(&g_acc[tid]);             // v_new
            s_rv[tid] = av;
            s_ri[tid] = tid;
            __syncthreads();
            for (int off = NTHR / 2; off > 0; off >>= 1) {
                if (tid < off) {
                    float ov = s_rv[tid + off]; int oi = s_ri[tid + off];
                    if (ov > s_rv[tid]) { s_rv[tid] = ov; s_ri[tid] = oi; }
                }
                __syncthreads();
            }
            const float vold = __ldcg(&g_v[tid]);
            const float vout = s_dn ? vold : av;              // s_dn = done at entry (set in P2)
            g_v[tid] = vout;
            if (tid == 0)
                *(volatile int*)&g_done = s_dn | (s_ri[0] == *(volatile int*)&g_tgt);
            if (s == STEPS - 1) out[tid] = vout;              // v_final
        }
        grid_sync();
    }
}

extern "C" void kernel_launch(void* const* d_in, const int* in_sizes, int n_in,
                              void* d_out, int out_size) {
    (void)in_sizes; (void)n_in; (void)out_size;
    const float* v_src    = (const float*)d_in[0];
    const float* v_target = (const float*)d_in[1];
    const float* omegas   = (const float*)d_in[2];
    const float* W1       = (const float*)d_in[3];
    const float* b1       = (const float*)d_in[4];
    const float* W2       = (const float*)d_in[5];
    const float* b2       = (const float*)d_in[6];
    const float* W3       = (const float*)d_in[7];
    const float* b3       = (const float*)d_in[8];
    const float* gumbel   = (const float*)d_in[9];
    float* out = (float*)d_out;

    petri_kernel<<<NBLK, NTHR>>>(v_src, v_target, omegas, W1, b1, W2, b2,
                                 W3, b3, gumbel, out);
}

// round 3
// speedup vs baseline: 1.7678x; 1.7678x over previous
#include <cuda_runtime.h>
#include <math.h>
#include <stdint.h>

#define NM    512
#define NT    64
#define NH1   256
#define NH2   128
#define STEPS 20
#define NBLK  64          // 8 clusters x 8 CTAs; all co-resident (<= SM count)
#define NTHR  512
#define CLN   8           // cluster size; cluster 0 (bids 0..7) runs MLP+Taylor
#define RPC   64          // Omega rows per cluster CTA (64*512*4B = 128KB smem)
#define NTAY  8           // Taylor degree; remainder < 5e-9 at ||Omega|| <= 0.5
#define SOFT_EPS 1e-7f    // skip softmax terms below this (error <= ~3e-6/step)
#define DSMEM_BYTES (RPC * NM * 4)   // 131072

// ----------------- device scratch (allocation is forbidden) -----------------
__device__ __align__(16) float g_Omega[2][NM * NM];   // double-buffered
__device__ float g_softv[STEPS][NT];
__device__ int   g_softi[STEPS][NT];
__device__ int   g_softn[STEPS];
__device__ unsigned g_soft_seq;          // step s published when == s+1
__device__ unsigned g_form[STEPS];       // formation arrivals per step
__device__ unsigned g_cnt, g_gen;        // init grid barrier (replay-safe)

// ----------------------------- ptx helpers ----------------------------------
__device__ __forceinline__ unsigned smem_u32(const void* p) {
    unsigned r;
    asm("{ .reg .u64 t; cvta.to.shared.u64 t, %1; cvt.u32.u64 %0, t; }"
        : "=r"(r) : "l"(p));
    return r;
}
__device__ __forceinline__ unsigned mapa_u32(unsigned a, unsigned rank) {
    unsigned r;
    asm("mapa.shared::cluster.u32 %0, %1, %2;" : "=r"(r) : "r"(a), "r"(rank));
    return r;
}
__device__ __forceinline__ void st_cluster(unsigned a, float v) {
    asm volatile("st.shared::cluster.f32 [%0], %1;" :: "r"(a), "f"(v) : "memory");
}
#define CLUSTER_SYNC() do { \
    asm volatile("barrier.cluster.arrive.aligned;" ::: "memory"); \
    asm volatile("barrier.cluster.wait.aligned;"   ::: "memory"); } while (0)

// One grid barrier per launch (orders the flag resets). Replay-safe: gen is
// monotonic, cnt self-resets.
__device__ __forceinline__ void grid_sync() {
    __syncthreads();
    if (threadIdx.x == 0) {
        __threadfence();
        unsigned gen = *(volatile unsigned*)&g_gen;
        if (atomicAdd(&g_cnt, 1u) == NBLK - 1u) {
            g_cnt = 0u;
            __threadfence();
            *(volatile unsigned*)&g_gen = gen + 1u;
        } else {
            while (*(volatile unsigned*)&g_gen == gen) { }
        }
        __threadfence();
    }
    __syncthreads();
}

__global__ void __launch_bounds__(NTHR, 1) __cluster_dims__(CLN, 1, 1)
petri_kernel(const float* __restrict__ v_src,  const float* __restrict__ v_target,
             const float* __restrict__ omegas, const float* __restrict__ W1,
             const float* __restrict__ b1,     const float* __restrict__ W2,
             const float* __restrict__ b2,     const float* __restrict__ W3,
             const float* __restrict__ b3,     const float* __restrict__ gumbel,
             float* __restrict__ out)
{
    extern __shared__ float s_O[];            // [RPC][NM] (cluster-0 CTAs only)
    __shared__ float s_t[2][NM];              // Taylor term ping-pong (replicated)
    __shared__ float s_acc[NM];               // expm action accumulator
    __shared__ float s_v[NM];                 // current state (replicated)
    __shared__ float s_vt[NM];                // v_target
    __shared__ float s_h1p[CLN * NH1];        // L1 partials (gathered in CTA0)
    __shared__ float s_h1[NH1];
    __shared__ float s_h2[NH2];
    __shared__ float s_red[NTHR];
    __shared__ int   s_ri[NTHR];
    __shared__ float s_sm[NT];
    __shared__ float s_fv[NT];
    __shared__ int   s_fi[NT];
    __shared__ int   s_done, s_n;
    __shared__ float s_scal;

    const int tid  = threadIdx.x;
    const int bid  = blockIdx.x;
    const int lane = tid & 31;
    const int warp = tid >> 5;
    const bool incl = (bid < CLN);            // member of cluster 0
    const int  rank = bid;                    // == cluster_ctarank when incl

    // -------- per-launch reset of flags (ordered by the single grid barrier) --------
    if (bid == 0 && tid == 0) {
        g_soft_seq = 0u;
        for (int s = 0; s < STEPS; ++s) g_form[s] = 0u;
    }
    int tgt = 0;
    if (incl) {
        s_vt[tid] = v_target[tid];
        s_v[tid]  = v_src[tid];
        if (tid == 0) s_done = 0;
        __syncthreads();
        s_red[tid] = s_vt[tid];
        s_ri[tid]  = tid;
        __syncthreads();
        for (int off = NTHR / 2; off > 0; off >>= 1) {
            if (tid < off) {
                float ov = s_red[tid + off]; int oi = s_ri[tid + off];
                if (ov > s_red[tid]) { s_red[tid] = ov; s_ri[tid] = oi; }
            }
            __syncthreads();
        }
        tgt = s_ri[0];                        // first-index tie-break (matches argmax)
        __syncthreads();
    }
    grid_sync();

    // ------------------------------------ scan ------------------------------------
    for (int s = 0; s < STEPS; ++s) {
        const int buf = s & 1;

        if (incl) {
            const int dn = s_done;            // done at step entry

            // ---- (A) MLP layer 1: CTA r covers x rows [128r, 128r+128) ----
            {
                const int j    = tid & (NH1 - 1);
                const int half = tid >> 8;                 // 0/1
                const int i0   = half * 64;
                const float* xs = (rank < 4) ? (s_v + rank * 128)
                                             : (s_vt + (rank - 4) * 128);
                const float* w = W1 + (size_t)(rank * 128 + i0) * NH1 + j;
                float p = 0.f;
                #pragma unroll 8
                for (int i = 0; i < 64; ++i) p += xs[i0 + i] * w[i * NH1];
                s_red[tid] = p;
            }
            __syncthreads();
            if (tid < NH1) {
                float p = s_red[tid] + s_red[tid + NH1];
                unsigned a = smem_u32(&s_h1p[rank * NH1 + tid]);
                st_cluster(mapa_u32(a, 0u), p);            // gather into CTA0
            }
            CLUSTER_SYNC();

            // ---- (B) MLP tail + gumbel softmax + publish (CTA0 only) ----
            if (rank == 0) {
                if (tid < NH1) {
                    float h = b1[tid];
                    #pragma unroll
                    for (int r = 0; r < CLN; ++r) h += s_h1p[r * NH1 + tid];
                    s_h1[tid] = fmaxf(h, 0.f);
                }
                __syncthreads();
                {   // L2: 128 outs x 256 in
                    const int j = tid & (NH2 - 1), part = tid >> 7;
                    const float* w = W2 + (size_t)(part * 64) * NH2 + j;
                    const float* h = s_h1 + part * 64;
                    float p = 0.f;
                    #pragma unroll 8
                    for (int i = 0; i < 64; ++i) p += h[i] * w[i * NH2];
                    s_red[tid] = p;
                }
                __syncthreads();
                if (tid < NH2) {
                    float h = s_red[tid] + s_red[tid + NH2] + s_red[tid + 2 * NH2]
                            + s_red[tid + 3 * NH2] + b2[tid];
                    s_h2[tid] = fmaxf(h, 0.f);
                }
                __syncthreads();
                {   // L3: 64 outs x 128 in
                    const int j = tid & (NT - 1), part = tid >> 6;  // 8 parts x 16
                    const float* w = W3 + (size_t)(part * 16) * NT + j;
                    const float* h = s_h2 + part * 16;
                    float p = 0.f;
                    #pragma unroll
                    for (int i = 0; i < 16; ++i) p += h[i] * w[i * NT];
                    s_red[tid] = p;
                }
                __syncthreads();
                if (tid < NT) {
                    float lg = b3[tid];
                    #pragma unroll
                    for (int q = 0; q < 8; ++q) lg += s_red[tid + q * NT];
                    out[NM + s * NT + tid] = dn ? 0.f : lg;   // logits (zeroed if done)
                    s_sm[tid] = lg + gumbel[s * NT + tid];    // TAU = 1
                }
                __syncthreads();
                if (tid == 0) {
                    float mx = s_sm[0];
                    for (int t = 1; t < NT; ++t) mx = fmaxf(mx, s_sm[t]);
                    s_scal = mx;
                }
                __syncthreads();
                if (tid < NT) s_sm[tid] = expf(s_sm[tid] - s_scal);
                __syncthreads();
                if (tid == 0) {
                    float ss = 0.f;
                    for (int t = 0; t < NT; ++t) ss += s_sm[t];
                    const float inv = 1.f / ss;
                    int n = 0;
                    for (int t = 0; t < NT; ++t) {
                        const float v = s_sm[t] * inv;
                        if (v >= SOFT_EPS) { g_softi[s][n] = t; g_softv[s][n] = v; ++n; }
                    }
                    g_softn[s] = n;
                    __threadfence();
                    *(volatile unsigned*)&g_soft_seq = (unsigned)(s + 1);  // release
                }
            }
        }

        // ---- (C) Omega formation (all 64 blocks): Omega = sum_active soft_t * A_t ----
        if (tid == 0) {
            while (*(volatile unsigned*)&g_soft_seq < (unsigned)(s + 1)) { }
            s_n = __ldcg(&g_softn[s]);
            __threadfence();
        }
        __syncthreads();
        const int n = s_n;
        if (tid < n) { s_fi[tid] = __ldcg(&g_softi[s][tid]); s_fv[tid] = __ldcg(&g_softv[s][tid]); }
        __syncthreads();
        {
            const float4* om4 = (const float4*)omegas;
            float4* O4 = ((float4*)g_Omega[buf]) + bid * 1024;
            float4 a0 = make_float4(0.f, 0.f, 0.f, 0.f), a1 = a0;
            #pragma unroll 4
            for (int q = 0; q < n; ++q) {
                const float sc = s_fv[q];
                const float4* src = om4 + (size_t)s_fi[q] * (NM * NM / 4) + bid * 1024;
                const float4 w0 = __ldg(src + tid), w1 = __ldg(src + tid + 512);
                a0.x += sc * w0.x; a0.y += sc * w0.y; a0.z += sc * w0.z; a0.w += sc * w0.w;
                a1.x += sc * w1.x; a1.y += sc * w1.y; a1.z += sc * w1.z; a1.w += sc * w1.w;
            }
            O4[tid] = a0; O4[tid + 512] = a1;
        }
        __threadfence();
        __syncthreads();
        if (tid == 0) atomicAdd(&g_form[s], 1u);   // REDG arrival

        if (incl) {
            // ---- (D) wait for full Omega, copy slice to smem ----
            if (tid == 0) {
                while (*(volatile unsigned*)&g_form[s] < (unsigned)NBLK) { }
                __threadfence();
            }
            __syncthreads();
            {
                const float4* src = ((const float4*)g_Omega[buf]) + rank * (RPC * NM / 4);
                float4* dst = (float4*)s_O;
                #pragma unroll
                for (int q = 0; q < 16; ++q)
                    dst[tid + 512 * q] = __ldcg(src + tid + 512 * q);
            }
            s_acc[tid] = s_v[tid];
            __syncthreads();

            // ---- (E) Taylor action: t_k = Omega t_{k-1} / k ; acc += t_k ----
            #pragma unroll
            for (int k = 1; k <= NTAY; ++k) {
                const float* src = (k == 1) ? s_v : s_t[(k - 1) & 1];
                const float invk = 1.0f / (float)k;
                #pragma unroll
                for (int rr = 0; rr < 4; ++rr) {           // 16 warps x 4 rows
                    const int row = warp * 4 + rr;
                    const float4* Or = ((const float4*)s_O) + row * (NM / 4);
                    const float4* sv = (const float4*)src;
                    float p = 0.f;
                    #pragma unroll
                    for (int q = 0; q < 4; ++q) {
                        const int j = lane + 32 * q;
                        const float4 o = Or[j], x = sv[j];
                        p += o.x * x.x + o.y * x.y + o.z * x.z + o.w * x.w;
                    }
                    #pragma unroll
                    for (int off = 16; off > 0; off >>= 1)
                        p += __shfl_down_sync(0xffffffffu, p, off);
                    if (lane == 0) s_red[row] = p * invk;
                }
                __syncthreads();
                {   // broadcast my 64 values into every peer's s_t[k&1]
                    const int m = tid & 63;
                    const unsigned dr = (unsigned)(tid >> 6);
                    unsigned a = smem_u32(&s_t[k & 1][rank * 64 + m]);
                    st_cluster(mapa_u32(a, dr), s_red[m]);
                }
                CLUSTER_SYNC();                            // release + whole-CTA barrier
                s_acc[tid] += s_t[k & 1][tid];
            }

            // ---- (F) done_new = done | (argmax(v_new)==tgt); v = done ? v : v_new ----
            const float vn = s_acc[tid];
            s_red[tid] = vn; s_ri[tid] = tid;
            __syncthreads();
            for (int off = NTHR / 2; off > 0; off >>= 1) {
                if (tid < off) {
                    float ov = s_red[tid + off]; int oi = s_ri[tid + off];
                    if (ov > s_red[tid]) { s_red[tid] = ov; s_ri[tid] = oi; }
                }
                __syncthreads();
            }
            const int dn0 = s_done;                        // entry done
            s_v[tid] = dn0 ? s_v[tid] : vn;
            if (tid == 0 && s_ri[0] == tgt) s_done = 1;
            __syncthreads();
            if (rank == 0 && s == STEPS - 1) out[tid] = s_v[tid];   // v_final
        }
    }
}

extern "C" void kernel_launch(void* const* d_in, const int* in_sizes, int n_in,
                              void* d_out, int out_size) {
    (void)in_sizes; (void)n_in; (void)out_size;
    const float* v_src    = (const float*)d_in[0];
    const float* v_target = (const float*)d_in[1];
    const float* omegas   = (const float*)d_in[2];
    const float* W1       = (const float*)d_in[3];
    const float* b1       = (const float*)d_in[4];
    const float* W2       = (const float*)d_in[5];
    const float* b2       = (const float*)d_in[6];
    const float* W3       = (const float*)d_in[7];
    const float* b3       = (const float*)d_in[8];
    const float* gumbel   = (const float*)d_in[9];
    float* out = (float*)d_out;

    cudaFuncSetAttribute(petri_kernel, cudaFuncAttributeMaxDynamicSharedMemorySize,
                         DSMEM_BYTES);
    petri_kernel<<<NBLK, NTHR, DSMEM_BYTES>>>(v_src, v_target, omegas, W1, b1,
                                              W2, b2, W3, b3, gumbel, out);
}

// round 5
// speedup vs baseline: 2.4952x; 1.4115x over previous
#include <cuda_runtime.h>
#include <math.h>
#include <stdint.h>

#define NM    512
#define NT    64
#define NH1   256
#define NH2   128
#define STEPS 20
#define NBLK  96          // 12 clusters x 8 CTAs; tiny smem -> comfortable residency
#define NTHR  512
#define CLN   8           // cluster 0 (bids 0..7) runs MLP + Taylor
#define NTAY  6           // Taylor degree; remainder < 7.5e-7/step at ||Omega|| <= 0.45
#define SOFT_EPS 1e-7f
#define NM4   (NM * NM / 4)   // 65536 float4 elements of Omega

// ----------------- device scratch (allocation is forbidden) -----------------
__device__ __align__(16) float g_Omega[NM * NM];
__device__ float g_softv[STEPS][NT];
__device__ int   g_softi[STEPS][NT];
__device__ int   g_softn[STEPS];           // -1 => step skipped (done)
__device__ unsigned g_soft_seq;            // step s published when == s+1
__device__ unsigned g_form[STEPS];         // formation arrivals (NBLK each)
__device__ unsigned g_cnt, g_gen;          // init grid barrier (replay-safe)

// ----------------------------- ptx helpers ----------------------------------
__device__ __forceinline__ unsigned smem_u32(const void* p) {
    unsigned r;
    asm("{ .reg .u64 t; cvta.to.shared.u64 t, %1; cvt.u32.u64 %0, t; }"
        : "=r"(r) : "l"(p));
    return r;
}
__device__ __forceinline__ unsigned mapa_u32(unsigned a, unsigned rank) {
    unsigned r;
    asm("mapa.shared::cluster.u32 %0, %1, %2;" : "=r"(r) : "r"(a), "r"(rank));
    return r;
}
__device__ __forceinline__ void st_cluster(unsigned a, float v) {
    asm volatile("st.shared::cluster.f32 [%0], %1;" :: "r"(a), "f"(v) : "memory");
}
#define CLUSTER_SYNC() do { \
    asm volatile("barrier.cluster.arrive.aligned;" ::: "memory"); \
    asm volatile("barrier.cluster.wait.aligned;"   ::: "memory"); } while (0)

// One grid barrier per launch (orders the per-launch flag resets). Replay-safe.
__device__ __forceinline__ void grid_sync() {
    __syncthreads();
    if (threadIdx.x == 0) {
        __threadfence();
        unsigned gen = *(volatile unsigned*)&g_gen;
        if (atomicAdd(&g_cnt, 1u) == NBLK - 1u) {
            g_cnt = 0u;
            __threadfence();
            *(volatile unsigned*)&g_gen = gen + 1u;
        } else {
            while (*(volatile unsigned*)&g_gen == gen) { }
        }
        __threadfence();
    }
    __syncthreads();
}

__global__ void __launch_bounds__(NTHR, 1) __cluster_dims__(CLN, 1, 1)
petri_kernel(const float* __restrict__ v_src,  const float* __restrict__ v_target,
             const float* __restrict__ omegas, const float* __restrict__ W1,
             const float* __restrict__ b1,     const float* __restrict__ W2,
             const float* __restrict__ b2,     const float* __restrict__ W3,
             const float* __restrict__ b3,     const float* __restrict__ gumbel,
             float* __restrict__ out)
{
    __shared__ __align__(16) float s_t[2][NM];   // Taylor term ping-pong (replicated)
    __shared__ __align__(16) float s_v[NM];      // current state (replicated)
    __shared__ __align__(16) float s_p[2048];    // MLP partials (reused per layer)
    __shared__ float s_hg[CLN * NH1];            // L1 partials gathered in CTA0
    __shared__ float s_h1t[NH1];                 // precomputed v_target @ W1-half
    __shared__ float s_h1[NH1];
    __shared__ float s_h2[NH2];
    __shared__ float s_brd[64];                  // Taylor broadcast staging
    __shared__ float s_sm[NT];
    __shared__ float s_fv[NT];
    __shared__ int   s_fi[NT];
    __shared__ float s_wred[16];
    __shared__ int   s_wri[16];
    __shared__ int   s_done, s_n, s_tgt;
    __shared__ float s_scal;

    const int tid  = threadIdx.x;
    const int bid  = blockIdx.x;
    const int lane = tid & 31;
    const int warp = tid >> 5;
    const bool incl = (bid < CLN);               // member of cluster 0
    const int  rank = bid;                       // cluster rank when incl

    const float4* W14 = (const float4*)W1;
    const float4* W24 = (const float4*)W2;
    const float4* W34 = (const float4*)W3;

    // ---------------- per-launch reset (ordered by the single grid barrier) ----------------
    if (bid == 0 && tid == 0) {
        g_soft_seq = 0u;
        for (int s = 0; s < STEPS; ++s) g_form[s] = 0u;
    }
    if (incl) {
        s_v[tid] = v_src[tid];
        if (tid == 0) s_done = 0;
        // tgt = argmax(v_target), first-index tie-break
        {
            float bv = v_target[tid]; int bi = tid;
            #pragma unroll
            for (int off = 16; off > 0; off >>= 1) {
                float ov = __shfl_down_sync(0xffffffffu, bv, off);
                int   oi = __shfl_down_sync(0xffffffffu, bi, off);
                if (ov > bv) { bv = ov; bi = oi; }
            }
            if (lane == 0) { s_wred[warp] = bv; s_wri[warp] = bi; }
        }
        __syncthreads();
        if (tid == 0) {
            float mv = s_wred[0]; int mi = s_wri[0];
            #pragma unroll
            for (int w = 1; w < 16; ++w)
                if (s_wred[w] > mv) { mv = s_wred[w]; mi = s_wri[w]; }
            s_tgt = mi;
        }
        // precompute target half of MLP L1: rows 512+64r .. 512+64r+64 of W1
        {
            const int u = tid & 63, part = tid >> 6;   // 8 parts x 8 rows
            float4 a = make_float4(0.f, 0.f, 0.f, 0.f);
            #pragma unroll
            for (int ii = 0; ii < 8; ++ii) {
                const int vr  = 64 * rank + part * 8 + ii;
                const float x = v_target[vr];
                const float4 w = __ldg(&W14[(size_t)(NM + vr) * 64 + u]);
                a.x += x * w.x; a.y += x * w.y; a.z += x * w.z; a.w += x * w.w;
            }
            ((float4*)s_p)[part * 64 + u] = a;
        }
        __syncthreads();
        if (tid < NH1) {
            float pj = 0.f;
            #pragma unroll
            for (int r = 0; r < 8; ++r) pj += s_p[r * NH1 + tid];
            st_cluster(mapa_u32(smem_u32(&s_hg[rank * NH1 + tid]), 0u), pj);
        }
        CLUSTER_SYNC();
        if (rank == 0 && tid < NH1) {
            float h = 0.f;
            #pragma unroll
            for (int r = 0; r < CLN; ++r) h += s_hg[r * NH1 + tid];
            s_h1t[tid] = h;
        }
        CLUSTER_SYNC();   // protect s_hg before step-0 reuse
    }
    grid_sync();

    // ------------------------------------ scan ------------------------------------
    for (int s = 0; s < STEPS; ++s) {
        if (incl) {
            const int dn = s_done;               // done at step entry
            if (!dn) {
                // ---- (A) MLP L1, v half: CTA r covers v rows [64r, 64r+64) ----
                {
                    const int u = tid & 63, part = tid >> 6;
                    float4 a = make_float4(0.f, 0.f, 0.f, 0.f);
                    #pragma unroll
                    for (int ii = 0; ii < 8; ++ii) {
                        const int vr  = 64 * rank + part * 8 + ii;
                        const float x = s_v[vr];
                        const float4 w = __ldg(&W14[(size_t)vr * 64 + u]);
                        a.x += x * w.x; a.y += x * w.y; a.z += x * w.z; a.w += x * w.w;
                    }
                    ((float4*)s_p)[part * 64 + u] = a;
                }
                __syncthreads();
                if (tid < NH1) {
                    float pj = 0.f;
                    #pragma unroll
                    for (int r = 0; r < 8; ++r) pj += s_p[r * NH1 + tid];
                    st_cluster(mapa_u32(smem_u32(&s_hg[rank * NH1 + tid]), 0u), pj);
                }
                CLUSTER_SYNC();

                // ---- (B) MLP tail + gumbel softmax + publish (CTA0 only) ----
                if (rank == 0) {
                    if (tid < NH1) {
                        float h = __ldg(&b1[tid]) + s_h1t[tid];
                        #pragma unroll
                        for (int r = 0; r < CLN; ++r) h += s_hg[r * NH1 + tid];
                        s_h1[tid] = fmaxf(h, 0.f);
                    }
                    __syncthreads();
                    {   // L2: 128 outs x 256 in, 16 parts x 16 rows
                        const int u = tid & 31, part = tid >> 5;
                        float4 a = make_float4(0.f, 0.f, 0.f, 0.f);
                        #pragma unroll
                        for (int ii = 0; ii < 16; ++ii) {
                            const int i = part * 16 + ii;
                            const float hv = s_h1[i];
                            const float4 w = __ldg(&W24[(size_t)i * 32 + u]);
                            a.x += hv * w.x; a.y += hv * w.y; a.z += hv * w.z; a.w += hv * w.w;
                        }
                        ((float4*)s_p)[part * 32 + u] = a;
                    }
                    __syncthreads();
                    if (tid < NH2) {
                        float h = __ldg(&b2[tid]);
                        #pragma unroll
                        for (int p = 0; p < 16; ++p) h += s_p[p * NH2 + tid];
                        s_h2[tid] = fmaxf(h, 0.f);
                    }
                    __syncthreads();
                    {   // L3: 64 outs x 128 in, 32 parts x 4 rows
                        const int u = tid & 15, part = tid >> 4;
                        float4 a = make_float4(0.f, 0.f, 0.f, 0.f);
                        #pragma unroll
                        for (int ii = 0; ii < 4; ++ii) {
                            const int i = part * 4 + ii;
                            const float hv = s_h2[i];
                            const float4 w = __ldg(&W34[(size_t)i * 16 + u]);
                            a.x += hv * w.x; a.y += hv * w.y; a.z += hv * w.z; a.w += hv * w.w;
                        }
                        ((float4*)s_p)[part * 16 + u] = a;
                    }
                    __syncthreads();
                    if (tid < NT) {
                        float lg = __ldg(&b3[tid]);
                        #pragma unroll
                        for (int p = 0; p < 32; ++p) lg += s_p[p * NT + tid];
                        out[NM + s * NT + tid] = lg;                 // not done here
                        s_sm[tid] = lg + __ldg(&gumbel[s * NT + tid]); // TAU = 1
                    }
                    __syncthreads();
                    if (tid == 0) {
                        float mx = s_sm[0];
                        for (int t = 1; t < NT; ++t) mx = fmaxf(mx, s_sm[t]);
                        s_scal = mx;
                    }
                    __syncthreads();
                    if (tid < NT) s_sm[tid] = expf(s_sm[tid] - s_scal);
                    __syncthreads();
                    if (tid == 0) {
                        float ss = 0.f;
                        for (int t = 0; t < NT; ++t) ss += s_sm[t];
                        const float inv = 1.f / ss;
                        int n = 0;
                        for (int t = 0; t < NT; ++t) {
                            const float v = s_sm[t] * inv;
                            if (v >= SOFT_EPS) { g_softi[s][n] = t; g_softv[s][n] = v; ++n; }
                        }
                        g_softn[s] = n;
                        __threadfence();
                        *(volatile unsigned*)&g_soft_seq = (unsigned)(s + 1);
                    }
                }
            } else {
                // ---- done: zeros for logits, frozen v, publish skip ----
                if (rank == 0) {
                    if (tid < NT) out[NM + s * NT + tid] = 0.f;
                    if (s == STEPS - 1) out[tid] = s_v[tid];
                    if (tid == 0) {
                        g_softn[s] = -1;
                        __threadfence();
                        *(volatile unsigned*)&g_soft_seq = (unsigned)(s + 1);
                    }
                }
            }
        }

        // ---- (C) wait for soft publication (all blocks) ----
        if (tid == 0) {
            while (*(volatile unsigned*)&g_soft_seq < (unsigned)(s + 1)) { }
            s_n = __ldcg(&g_softn[s]);
            __threadfence();
        }
        __syncthreads();
        const int n = s_n;

        // ---- (D) Omega formation (all 96 blocks, balanced chunks) ----
        if (n >= 0) {
            if (tid < n) { s_fi[tid] = __ldcg(&g_softi[s][tid]); s_fv[tid] = __ldcg(&g_softv[s][tid]); }
            __syncthreads();
            const int base = bid * 682 + (bid < 64 ? bid : 64);
            const int cnt  = 682 + (bid < 64 ? 1 : 0);
            const float4* om4 = (const float4*)omegas;
            for (int e = base + tid; e < base + cnt; e += NTHR) {
                float4 a0 = make_float4(0.f, 0.f, 0.f, 0.f), a1 = a0;
                int q = 0;
                for (; q + 1 < n; q += 2) {
                    const float c0 = s_fv[q], c1 = s_fv[q + 1];
                    const float4 w0 = __ldg(om4 + (size_t)s_fi[q]     * NM4 + e);
                    const float4 w1 = __ldg(om4 + (size_t)s_fi[q + 1] * NM4 + e);
                    a0.x += c0 * w0.x; a0.y += c0 * w0.y; a0.z += c0 * w0.z; a0.w += c0 * w0.w;
                    a1.x += c1 * w1.x; a1.y += c1 * w1.y; a1.z += c1 * w1.z; a1.w += c1 * w1.w;
                }
                if (q < n) {
                    const float c0 = s_fv[q];
                    const float4 w0 = __ldg(om4 + (size_t)s_fi[q] * NM4 + e);
                    a0.x += c0 * w0.x; a0.y += c0 * w0.y; a0.z += c0 * w0.z; a0.w += c0 * w0.w;
                }
                a0.x += a1.x; a0.y += a1.y; a0.z += a1.z; a0.w += a1.w;
                ((float4*)g_Omega)[e] = a0;
            }
            __threadfence();
            __syncthreads();
            if (tid == 0) atomicAdd(&g_form[s], 1u);
        }

        // ---- (E) Taylor action from registers (cluster 0, active steps only) ----
        if (incl && n >= 0) {
            if (tid == 0) {
                while (*(volatile unsigned*)&g_form[s] < (unsigned)NBLK) { }
                __threadfence();
            }
            __syncthreads();

            // per-thread Omega tile: rows 64*rank + warp*4 + rr, cols lane*4 + 128*q + e
            float4 O[4][4];
            {
                const float4* G4 = (const float4*)g_Omega;
                const int rbase = 64 * rank + warp * 4;
                #pragma unroll
                for (int rr = 0; rr < 4; ++rr)
                    #pragma unroll
                    for (int q = 0; q < 4; ++q)
                        O[rr][q] = __ldcg(&G4[(size_t)(rbase + rr) * 128 + lane + 32 * q]);
            }
            float accv = s_v[tid];
            #pragma unroll
            for (int k = 1; k <= NTAY; ++k) {
                const float4* src4 = (k == 1) ? (const float4*)s_v
                                              : (const float4*)s_t[(k - 1) & 1];
                const float4 t0 = src4[lane], t1 = src4[lane + 32],
                             t2 = src4[lane + 64], t3 = src4[lane + 96];
                const float invk = 1.0f / (float)k;
                #pragma unroll
                for (int rr = 0; rr < 4; ++rr) {
                    float p = O[rr][0].x * t0.x + O[rr][0].y * t0.y + O[rr][0].z * t0.z + O[rr][0].w * t0.w
                            + O[rr][1].x * t1.x + O[rr][1].y * t1.y + O[rr][1].z * t1.z + O[rr][1].w * t1.w
                            + O[rr][2].x * t2.x + O[rr][2].y * t2.y + O[rr][2].z * t2.z + O[rr][2].w * t2.w
                            + O[rr][3].x * t3.x + O[rr][3].y * t3.y + O[rr][3].z * t3.z + O[rr][3].w * t3.w;
                    #pragma unroll
                    for (int off = 16; off > 0; off >>= 1)
                        p += __shfl_down_sync(0xffffffffu, p, off);
                    if (lane == 0) s_brd[warp * 4 + rr] = p * invk;
                }
                __syncthreads();
                {   // broadcast my 64 rows into every peer's (and own) s_t[k&1]
                    const int m = tid & 63;
                    const unsigned dr = (unsigned)(tid >> 6);
                    st_cluster(mapa_u32(smem_u32(&s_t[k & 1][64 * rank + m]), dr), s_brd[m]);
                }
                CLUSTER_SYNC();
                accv += s_t[k & 1][tid];
            }

            // ---- (F) done_new = (argmax(v_new)==tgt); v = v_new (dn was 0) ----
            const float vn = accv;
            {
                float bv = vn; int bi = tid;
                #pragma unroll
                for (int off = 16; off > 0; off >>= 1) {
                    float ov = __shfl_down_sync(0xffffffffu, bv, off);
                    int   oi = __shfl_down_sync(0xffffffffu, bi, off);
                    if (ov > bv) { bv = ov; bi = oi; }
                }
                if (lane == 0) { s_wred[warp] = bv; s_wri[warp] = bi; }
            }
            __syncthreads();
            s_v[tid] = vn;
            if (tid == 0) {
                float mv = s_wred[0]; int mi = s_wri[0];
                #pragma unroll
                for (int w = 1; w < 16; ++w)
                    if (s_wred[w] > mv) { mv = s_wred[w]; mi = s_wri[w]; }
                if (mi == s_tgt) s_done = 1;
            }
            __syncthreads();
            if (rank == 0 && s == STEPS - 1) out[tid] = vn;     // v_final
        }
    }
}

extern "C" void kernel_launch(void* const* d_in, const int* in_sizes, int n_in,
                              void* d_out, int out_size) {
    (void)in_sizes; (void)n_in; (void)out_size;
    const float* v_src    = (const float*)d_in[0];
    const float* v_target = (const float*)d_in[1];
    const float* omegas   = (const float*)d_in[2];
    const float* W1       = (const float*)d_in[3];
    const float* b1       = (const float*)d_in[4];
    const float* W2       = (const float*)d_in[5];
    const float* b2       = (const float*)d_in[6];
    const float* W3       = (const float*)d_in[7];
    const float* b3       = (const float*)d_in[8];
    const float* gumbel   = (const float*)d_in[9];
    float* out = (float*)d_out;

    petri_kernel<<<NBLK, NTHR>>>(v_src, v_target, omegas, W1, b1,
                                 W2, b2, W3, b3, gumbel, out);
}